// round 10
// baseline (speedup 1.0000x reference)
#include <cuda_runtime.h>

// ---------------------------------------------------------------------------
// B=16, N=7, Lq=256, Lp=512, D=768, S=12, Wq=200, Wp=400
// word slots: q 3200, p 6400, n 44800 -> 54400
// out floats: q_pooled[0,12288) p_pooled[12288,24576)
//             q_logits[24576,62976) p_logits[62976,139776) n_pooled[139776,225792)
//
// Sample-group pipeline (2 groups: q 8+8, p 8+8, n 56+56):
//   kA(g1) -> kB(g1) -> kmix[ kA(g2) || kC(g1) ] -> kB(g2) -> kC(g2)
// kA uses ldcg so each group's 107MB stream stays L2-resident for its kC,
// which reads in reverse order to hit the freshest lines first.
// ---------------------------------------------------------------------------
#define TOTAL_WORDS 54400
#define OFF_QPOOL 0
#define OFF_PPOOL 12288
#define OFF_QLOG  24576
#define OFF_PLOG  62976
#define OFF_NPOOL 139776

__device__ float g_acc[TOTAL_WORDS * 13];   // 12 logit sums + count
__device__ float g_coef[TOTAL_WORDS];

typedef unsigned long long u64;

__device__ __forceinline__ u64 pack2(float x) {
    u64 r; asm("mov.b64 %0, {%1, %1};" : "=l"(r) : "f"(x)); return r;
}
__device__ __forceinline__ u64 pack2(float lo, float hi) {
    u64 r; asm("mov.b64 %0, {%1, %2};" : "=l"(r) : "f"(lo), "f"(hi)); return r;
}
__device__ __forceinline__ void fma2(u64& a, u64 x, u64 y) {
    asm("fma.rn.f32x2 %0, %1, %2, %0;" : "+l"(a) : "l"(x), "l"(y));
}
__device__ __forceinline__ u64 add2(u64 x, u64 y) {
    u64 r; asm("add.rn.f32x2 %0, %1, %2;" : "=l"(r) : "l"(x), "l"(y)); return r;
}
__device__ __forceinline__ float2 unpack2(u64 v) {
    float2 r; asm("mov.b64 {%0, %1}, %2;" : "=f"(r.x), "=f"(r.y) : "l"(v)); return r;
}

// ---------------------------------------------------------------------------
// kA pass body (R6-proven): 16 tokens/warp-pass, sub=lane&7 covers a 128B
// row segment, grp=lane>>3 + tt*4 tokens, 3-buffer rotating prefetch
// (loads 2-3 compute blocks ahead), ldcg to leave L2 residue for kC.
// Weights: smem chunks [c][k*6+j], pitch 26 u64; conflict-free LDS.128.
// Pass numbering: q 0..255, p 256..767, n 768..4351  (16 tokens each).
// Group g1 = first half of each tensor's samples, g2 = second half.
// ---------------------------------------------------------------------------
#define WSLOT 26

#define KA_LD(I, V0, V1, V2, V3)                                               \
    {                                                                          \
        V0 = __ldcg((const float4*)(hbg +        (I) * 32));                   \
        V1 = __ldcg((const float4*)(hbg + 3072 + (I) * 32));                   \
        V2 = __ldcg((const float4*)(hbg + 6144 + (I) * 32));                   \
        V3 = __ldcg((const float4*)(hbg + 9216 + (I) * 32));                   \
    }

#define KA_COMPUTE(I, A0, A1, A2, A3)                                          \
    {                                                                          \
        const u64* wr = swl + (I) * (8 * WSLOT);                               \
        _Pragma("unroll")                                                      \
        for (int k = 0; k < 4; k++) {                                          \
            u64 h0 = pack2(((const float*)&A0)[k]);                            \
            u64 h1 = pack2(((const float*)&A1)[k]);                            \
            u64 hv2 = pack2(((const float*)&A2)[k]);                           \
            u64 h3 = pack2(((const float*)&A3)[k]);                            \
            ulonglong2 w01 = *(const ulonglong2*)(wr + k * 6);                 \
            ulonglong2 w23 = *(const ulonglong2*)(wr + k * 6 + 2);             \
            ulonglong2 w45 = *(const ulonglong2*)(wr + k * 6 + 4);             \
            fma2(acc[0][0], h0, w01.x); fma2(acc[0][1], h0, w01.y);            \
            fma2(acc[0][2], h0, w23.x); fma2(acc[0][3], h0, w23.y);            \
            fma2(acc[0][4], h0, w45.x); fma2(acc[0][5], h0, w45.y);            \
            fma2(acc[1][0], h1, w01.x); fma2(acc[1][1], h1, w01.y);            \
            fma2(acc[1][2], h1, w23.x); fma2(acc[1][3], h1, w23.y);            \
            fma2(acc[1][4], h1, w45.x); fma2(acc[1][5], h1, w45.y);            \
            fma2(acc[2][0], hv2, w01.x); fma2(acc[2][1], hv2, w01.y);          \
            fma2(acc[2][2], hv2, w23.x); fma2(acc[2][3], hv2, w23.y);          \
            fma2(acc[2][4], hv2, w45.x); fma2(acc[2][5], hv2, w45.y);          \
            fma2(acc[3][0], h3, w01.x); fma2(acc[3][1], h3, w01.y);            \
            fma2(acc[3][2], h3, w23.x); fma2(acc[3][3], h3, w23.y);            \
            fma2(acc[3][4], h3, w45.x); fma2(acc[3][5], h3, w45.y);            \
        }                                                                      \
    }

__device__ __forceinline__ void ka_load_weights(u64* sw, const float* projw,
                                                int tid, int nthr) {
    for (int idx = tid; idx < 768 * 6; idx += nthr) {
        int d = idx / 6, j = idx % 6;
        sw[(d >> 2) * WSLOT + (d & 3) * 6 + j] =
            pack2(projw[d * 12 + 2 * j], projw[d * 12 + 2 * j + 1]);
    }
}

__device__ __forceinline__ void ka_pass(
    int p, const u64* swl, int sub, int grp,
    const float* __restrict__ qh, const float* __restrict__ ph, const float* __restrict__ nh,
    const int* __restrict__ qw, const int* __restrict__ pw, const int* __restrict__ nwid)
{
    const float* hid; const int* wid; int logL, W, wb, lp;
    if (p < 256)      { hid = qh; wid = qw;   logL = 8; W = 200; wb = 0;    lp = p; }
    else if (p < 768) { hid = ph; wid = pw;   logL = 9; W = 400; wb = 3200; lp = p - 256; }
    else              { hid = nh; wid = nwid; logL = 9; W = 400; wb = 9600; lp = p - 768; }

    const int tokBase = lp << 4;                 // 16 tokens
    const int m = tokBase >> logL;
    const float* hbg = hid + (size_t)tokBase * 768 + (size_t)grp * 768 + sub * 4;

    u64 acc[4][6];
    #pragma unroll
    for (int tt = 0; tt < 4; tt++)
        #pragma unroll
        for (int j = 0; j < 6; j++) acc[tt][j] = 0ull;

    float4 A0, A1, A2, A3, B0, B1, B2, B3, C0, C1, C2, C3;
    KA_LD(0, A0, A1, A2, A3);
    KA_LD(1, B0, B1, B2, B3);

    #pragma unroll 1
    for (int i = 0; i < 21; i += 3) {
        KA_LD(i + 2, C0, C1, C2, C3);
        KA_COMPUTE(i, A0, A1, A2, A3);
        KA_LD(i + 3, A0, A1, A2, A3);
        KA_COMPUTE(i + 1, B0, B1, B2, B3);
        KA_LD(i + 4, B0, B1, B2, B3);
        KA_COMPUTE(i + 2, C0, C1, C2, C3);
    }
    KA_LD(23, C0, C1, C2, C3);
    KA_COMPUTE(21, A0, A1, A2, A3);
    KA_COMPUTE(22, B0, B1, B2, B3);
    KA_COMPUTE(23, C0, C1, C2, C3);

    #pragma unroll
    for (int tt = 0; tt < 4; tt++)
        #pragma unroll
        for (int j = 0; j < 6; j++) {
            u64 v = acc[tt][j];
            v = add2(v, __shfl_xor_sync(0xffffffffu, v, 1));
            v = add2(v, __shfl_xor_sync(0xffffffffu, v, 2));
            v = add2(v, __shfl_xor_sync(0xffffffffu, v, 4));
            acc[tt][j] = v;
        }

    if (sub == 0) {
        #pragma unroll
        for (int tt = 0; tt < 4; tt++) {
            int tok = tokBase + grp + 4 * tt;
            float* ls = g_acc + (size_t)(wb + m * W + wid[tok]) * 13;
            #pragma unroll
            for (int j = 0; j < 6; j++) {
                float2 f = unpack2(acc[tt][j]);
                atomicAdd(ls + 2 * j,     f.x);
                atomicAdd(ls + 2 * j + 1, f.y);
            }
            atomicAdd(ls + 12, 1.0f);
        }
    }
}

// pass index for warp idx (0..2175) within group g
__device__ __forceinline__ int group_pass(int idx, int g) {
    if (g == 0) return idx < 128 ? idx : (idx < 384 ? 128 + idx : 384 + idx);
    return idx < 128 ? 128 + idx : (idx < 384 ? 384 + idx : 2176 + idx);
}

// ---------------------------------------------------------------------------
// Standalone kA for one group: 544 blocks x 128 (2176 warps = 2176 passes)
// ---------------------------------------------------------------------------
__global__ __launch_bounds__(128) void kA(
    const float* __restrict__ qh, const float* __restrict__ ph, const float* __restrict__ nh,
    const int* __restrict__ qw, const int* __restrict__ pw, const int* __restrict__ nwid,
    const float* __restrict__ projw, int g)
{
    __shared__ __align__(16) u64 sw[192 * WSLOT];   // 39936 B
    ka_load_weights(sw, projw, threadIdx.x, 128);
    __syncthreads();

    const int lane = threadIdx.x & 31;
    const int sub  = lane & 7;
    const int grp  = lane >> 3;
    const int gw   = (blockIdx.x * 128 + threadIdx.x) >> 5;
    const u64* swl = sw + sub * WSLOT;

    ka_pass(group_pass(gw, g), swl, sub, grp, qh, ph, nh, qw, pw, nwid);
}

// ---------------------------------------------------------------------------
// kC chunk decode for reversed-order group blocks (544 chunks per group):
// rc<32: q (8 samples x 4 slabs of 64 tok); rc<96: p (8 x 8); else n (56 x 8)
// ---------------------------------------------------------------------------
struct KCDesc { const float* hid; const int* wid; int L, wb, m, slab; float* po; };

__device__ __forceinline__ KCDesc kc_decode(
    int rc, int g,
    const float* qh, const float* ph, const float* nh,
    const int* qw, const int* pw, const int* nwid, float* out)
{
    KCDesc d;
    if (rc < 32) {
        d.m = (rc >> 2) + 8 * g; d.slab = rc & 3;
        d.hid = qh; d.wid = qw; d.L = 256;
        d.wb = d.m * 200; d.po = out + OFF_QPOOL + d.m * 768;
    } else if (rc < 96) {
        int b = rc - 32; d.m = (b >> 3) + 8 * g; d.slab = b & 7;
        d.hid = ph; d.wid = pw; d.L = 512;
        d.wb = 3200 + d.m * 400; d.po = out + OFF_PPOOL + d.m * 768;
    } else {
        int b = rc - 96; d.m = (b >> 3) + 56 * g; d.slab = b & 7;
        d.hid = nh; d.wid = nwid; d.L = 512;
        d.wb = 9600 + d.m * 400; d.po = out + OFF_NPOOL + d.m * 768;
    }
    return d;
}

// ---------------------------------------------------------------------------
// Mixed kernel: blocks 0..543 run kA(group 1); blocks 544..1087 run kC(group 0)
// in reversed chunk order (reads the L2-freshest g1 data first).
// 128 threads/block; kC role covers D=768 with tid*4 (512) + tid<64 tail.
// ---------------------------------------------------------------------------
__global__ __launch_bounds__(128) void kmix(
    const float* __restrict__ qh, const float* __restrict__ ph, const float* __restrict__ nh,
    const int* __restrict__ qw, const int* __restrict__ pw, const int* __restrict__ nwid,
    const float* __restrict__ projw, float* __restrict__ out)
{
    __shared__ __align__(16) u64 sw[192 * WSLOT];
    __shared__ float cf[64];
    const int tid = threadIdx.x;

    if (blockIdx.x < 544) {
        // ---- kA role, group 1 ----
        ka_load_weights(sw, projw, tid, 128);
        __syncthreads();
        const int lane = tid & 31;
        const int sub  = lane & 7;
        const int grp  = lane >> 3;
        const int gw   = (blockIdx.x * 128 + tid) >> 5;
        ka_pass(group_pass(gw, 1), sw + sub * WSLOT, sub, grp, qh, ph, nh, qw, pw, nwid);
    } else {
        // ---- kC role, group 0, reversed ----
        const int rc = 543 - (int)(blockIdx.x - 544);
        KCDesc d = kc_decode(rc, 0, qh, ph, nh, qw, pw, nwid, out);
        const int t0 = d.slab * 64;
        if (tid < 64) cf[tid] = g_coef[d.wb + d.wid[d.m * d.L + t0 + tid]];
        __syncthreads();

        const float* hp = d.hid + (size_t)(d.m * d.L + t0) * 768;
        const float* p0 = hp + tid * 4;
        const float* p1 = hp + 512 + tid * 4;
        float a0 = 0, a1 = 0, a2 = 0, a3 = 0;
        float b0 = 0, b1 = 0, b2 = 0, b3 = 0;
        #pragma unroll 4
        for (int tk = 0; tk < 64; tk++) {
            float cc = cf[tk];
            float4 v = *(const float4*)(p0 + (size_t)tk * 768);
            a0 += cc * v.x; a1 += cc * v.y; a2 += cc * v.z; a3 += cc * v.w;
            if (tid < 64) {
                float4 u = *(const float4*)(p1 + (size_t)tk * 768);
                b0 += cc * u.x; b1 += cc * u.y; b2 += cc * u.z; b3 += cc * u.w;
            }
        }
        float* o = d.po + tid * 4;
        atomicAdd(o + 0, a0); atomicAdd(o + 1, a1);
        atomicAdd(o + 2, a2); atomicAdd(o + 3, a3);
        if (tid < 64) {
            float* o2 = d.po + 512 + tid * 4;
            atomicAdd(o2 + 0, b0); atomicAdd(o2 + 1, b1);
            atomicAdd(o2 + 2, b2); atomicAdd(o2 + 3, b3);
        }
    }
}

// ---------------------------------------------------------------------------
// Kernel B for one group: 72 blocks (q 8, p 8, n 56) x 128 threads.
// ---------------------------------------------------------------------------
__global__ __launch_bounds__(128) void kB(const float* __restrict__ projb,
                                          const float* __restrict__ simp,
                                          float* __restrict__ out, int g)
{
    const int blk = blockIdx.x;
    int W, wb; float* lout = nullptr;
    if (blk < 8)       { int s = blk + 8 * g;        W = 200; wb = s * 200;        lout = out + OFF_QLOG + s * 200 * 12; }
    else if (blk < 16) { int s = (blk - 8) + 8 * g;  W = 400; wb = 3200 + s * 400; lout = out + OFF_PLOG + s * 400 * 12; }
    else               { int s = (blk - 16) + 56 * g; W = 400; wb = 9600 + s * 400; }

    __shared__ float impbuf[400];
    __shared__ float red[4];
    const int tid = threadIdx.x;

    float b[12], si[12];
    #pragma unroll
    for (int s = 0; s < 12; s++) { b[s] = projb[s]; si[s] = simp[s]; }

    for (int w = tid; w < W; w += 128) {
        const float* ls = g_acc + (size_t)(wb + w) * 13;
        float c = ls[12];
        float imp;
        if (c > 0.f) {
            float l[12], mx = -1e30f;
            float invc = 1.f / c;
            #pragma unroll
            for (int s = 0; s < 12; s++) {
                l[s] = ls[s] * invc + b[s];
                mx = fmaxf(mx, l[s]);
            }
            float se = 0.f, ai = 0.f;
            #pragma unroll
            for (int s = 0; s < 12; s++) {
                float e = __expf(l[s] - mx);
                se += e; ai += e * si[s];
            }
            imp = ai / se;
            if (lout) {
                #pragma unroll
                for (int s = 0; s < 12; s++) lout[w * 12 + s] = l[s];
            }
        } else {
            imp = -1e4f;
            if (lout) {
                #pragma unroll
                for (int s = 0; s < 12; s++) lout[w * 12 + s] = 0.f;
            }
        }
        impbuf[w] = imp;
    }
    __syncthreads();

    float mx = -1e30f;
    for (int w = tid; w < W; w += 128) mx = fmaxf(mx, impbuf[w]);
    #pragma unroll
    for (int o = 16; o; o >>= 1) mx = fmaxf(mx, __shfl_xor_sync(0xffffffffu, mx, o));
    if ((tid & 31) == 0) red[tid >> 5] = mx;
    __syncthreads();
    mx = fmaxf(fmaxf(red[0], red[1]), fmaxf(red[2], red[3]));
    __syncthreads();

    float se = 0.f;
    for (int w = tid; w < W; w += 128) se += __expf(impbuf[w] - mx);
    #pragma unroll
    for (int o = 16; o; o >>= 1) se += __shfl_xor_sync(0xffffffffu, se, o);
    if ((tid & 31) == 0) red[tid >> 5] = se;
    __syncthreads();
    se = red[0] + red[1] + red[2] + red[3];
    const float inv = 1.f / se;

    for (int w = tid; w < W; w += 128) {
        float c = g_acc[(size_t)(wb + w) * 13 + 12];
        g_coef[wb + w] = (c > 0.f) ? (__expf(impbuf[w] - mx) * inv) / c : 0.f;
    }
}

// ---------------------------------------------------------------------------
// Standalone kC for one group: 544 blocks x 192 threads, reversed order
// (reads the tail of the just-streamed kA group first -> L2 hits).
// ---------------------------------------------------------------------------
__global__ __launch_bounds__(192) void kC(
    const float* __restrict__ qh, const float* __restrict__ ph, const float* __restrict__ nh,
    const int* __restrict__ qw, const int* __restrict__ pw, const int* __restrict__ nwid,
    float* __restrict__ out, int g)
{
    const int rc = 543 - (int)blockIdx.x;
    KCDesc d = kc_decode(rc, g, qh, ph, nh, qw, pw, nwid, out);

    __shared__ float cf[64];
    const int tid = threadIdx.x;
    const int t0 = d.slab * 64;
    if (tid < 64) cf[tid] = g_coef[d.wb + d.wid[d.m * d.L + t0 + tid]];
    __syncthreads();

    const float* hp = d.hid + (size_t)(d.m * d.L + t0) * 768 + tid * 4;
    float ax = 0.f, ay = 0.f, az = 0.f, aw = 0.f;
    #pragma unroll 8
    for (int t = 0; t < 64; t++) {
        float c = cf[t];
        float4 v = *(const float4*)(hp + (size_t)t * 768);
        ax += c * v.x; ay += c * v.y; az += c * v.z; aw += c * v.w;
    }
    float* o = d.po + tid * 4;
    atomicAdd(o + 0, ax);
    atomicAdd(o + 1, ay);
    atomicAdd(o + 2, az);
    atomicAdd(o + 3, aw);
}

// ---------------------------------------------------------------------------
extern "C" void kernel_launch(void* const* d_in, const int* in_sizes, int n_in,
                              void* d_out, int out_size)
{
    const float* qh    = (const float*)d_in[0];
    const float* ph    = (const float*)d_in[1];
    const float* nh    = (const float*)d_in[2];
    const float* projw = (const float*)d_in[3];
    const float* projb = (const float*)d_in[4];
    const float* simp  = (const float*)d_in[5];
    const int*   qw    = (const int*)d_in[6];
    const int*   pw    = (const int*)d_in[7];
    const int*   nwid  = (const int*)d_in[8];
    float* out = (float*)d_out;

    void* pacc = nullptr; cudaGetSymbolAddress(&pacc, g_acc);
    cudaMemsetAsync(pacc, 0, sizeof(float) * TOTAL_WORDS * 13);
    cudaMemsetAsync(out + OFF_QPOOL, 0, sizeof(float) * 24576);   // q_pooled + p_pooled
    cudaMemsetAsync(out + OFF_NPOOL, 0, sizeof(float) * 86016);   // n_pooled

    kA  <<<544, 128>>>(qh, ph, nh, qw, pw, nwid, projw, 0);
    kB  <<<72, 128>>>(projb, simp, out, 0);
    kmix<<<1088, 128>>>(qh, ph, nh, qw, pw, nwid, projw, out);
    kB  <<<72, 128>>>(projb, simp, out, 1);
    kC  <<<544, 192>>>(qh, ph, nh, qw, pw, nwid, out, 1);
}

// round 11
// speedup vs baseline: 1.5306x; 1.5306x over previous
#include <cuda_runtime.h>

// ---------------------------------------------------------------------------
// B=16, N=7, Lq=256, Lp=512, D=768, S=12, Wq=200, Wp=400
// word slots: q 3200, p 6400, n 44800 -> 54400
// out floats: q_pooled[0,12288) p_pooled[12288,24576)
//             q_logits[24576,62976) p_logits[62976,139776) n_pooled[139776,225792)
// ---------------------------------------------------------------------------
#define TOTAL_WORDS 54400
#define OFF_QPOOL 0
#define OFF_PPOOL 12288
#define OFF_QLOG  24576
#define OFF_PLOG  62976
#define OFF_NPOOL 139776

// g_acc[w*16 + 0..11] = logit sums, [w*16+12] = count (pitch 16 for aligned
// float4 reads in kB; 13..15 unused)
__device__ float g_acc[TOTAL_WORDS * 16];
__device__ float g_coef[TOTAL_WORDS];

typedef unsigned long long u64;

__device__ __forceinline__ u64 pack2(float x) {
    u64 r; asm("mov.b64 %0, {%1, %1};" : "=l"(r) : "f"(x)); return r;
}
__device__ __forceinline__ u64 pack2(float lo, float hi) {
    u64 r; asm("mov.b64 %0, {%1, %2};" : "=l"(r) : "f"(lo), "f"(hi)); return r;
}
__device__ __forceinline__ void fma2(u64& a, u64 x, u64 y) {
    asm("fma.rn.f32x2 %0, %1, %2, %0;" : "+l"(a) : "l"(x), "l"(y));
}
__device__ __forceinline__ u64 add2(u64 x, u64 y) {
    u64 r; asm("add.rn.f32x2 %0, %1, %2;" : "=l"(r) : "l"(x), "l"(y)); return r;
}
__device__ __forceinline__ float2 unpack2(u64 v) {
    float2 r; asm("mov.b64 {%0, %1}, %2;" : "=f"(r.x), "=f"(r.y) : "l"(v)); return r;
}

// ---------------------------------------------------------------------------
// Kernel A (R6 geometry, ldcg): per-token projection h[768]@W[768x12] +
// segment atomics. sub=lane&7 covers d = sub*4 + 32*i + k; grp=lane>>3,
// tokens = grp + 4*tt, tt 0..3 -> 16 tokens/pass. 3 rotating register
// buffers, loads issued 2-3 compute blocks ahead. __ldcg leaves the stream
// L2-resident for kC (L2 = 126MB vs 214MB footprint -> ~59% kC hit rate).
// Weights: smem chunks [c][k*6+j], pitch 26 u64; conflict-free LDS.128
// (sub byte offsets mod 128 = {0,80,32,112,64,16,96,48}).
// Passes: 69632/16 = 4352; grid 544*4 warps = 2176 -> exactly 2 passes/warp.
// ---------------------------------------------------------------------------
#define WSLOT 26
#define NPASS_TOTAL 4352
#define KA_BLOCKS 544

#define KA_LD(I, V0, V1, V2, V3)                                               \
    {                                                                          \
        V0 = __ldcg((const float4*)(hbg +        (I) * 32));                   \
        V1 = __ldcg((const float4*)(hbg + 3072 + (I) * 32));                   \
        V2 = __ldcg((const float4*)(hbg + 6144 + (I) * 32));                   \
        V3 = __ldcg((const float4*)(hbg + 9216 + (I) * 32));                   \
    }

#define KA_COMPUTE(I, A0, A1, A2, A3)                                          \
    {                                                                          \
        const u64* wr = swl + (I) * (8 * WSLOT);                               \
        _Pragma("unroll")                                                      \
        for (int k = 0; k < 4; k++) {                                          \
            u64 h0 = pack2(((const float*)&A0)[k]);                            \
            u64 h1 = pack2(((const float*)&A1)[k]);                            \
            u64 hv2 = pack2(((const float*)&A2)[k]);                           \
            u64 h3 = pack2(((const float*)&A3)[k]);                            \
            ulonglong2 w01 = *(const ulonglong2*)(wr + k * 6);                 \
            ulonglong2 w23 = *(const ulonglong2*)(wr + k * 6 + 2);             \
            ulonglong2 w45 = *(const ulonglong2*)(wr + k * 6 + 4);             \
            fma2(acc[0][0], h0, w01.x); fma2(acc[0][1], h0, w01.y);            \
            fma2(acc[0][2], h0, w23.x); fma2(acc[0][3], h0, w23.y);            \
            fma2(acc[0][4], h0, w45.x); fma2(acc[0][5], h0, w45.y);            \
            fma2(acc[1][0], h1, w01.x); fma2(acc[1][1], h1, w01.y);            \
            fma2(acc[1][2], h1, w23.x); fma2(acc[1][3], h1, w23.y);            \
            fma2(acc[1][4], h1, w45.x); fma2(acc[1][5], h1, w45.y);            \
            fma2(acc[2][0], hv2, w01.x); fma2(acc[2][1], hv2, w01.y);          \
            fma2(acc[2][2], hv2, w23.x); fma2(acc[2][3], hv2, w23.y);          \
            fma2(acc[2][4], hv2, w45.x); fma2(acc[2][5], hv2, w45.y);          \
            fma2(acc[3][0], h3, w01.x); fma2(acc[3][1], h3, w01.y);            \
            fma2(acc[3][2], h3, w23.x); fma2(acc[3][3], h3, w23.y);            \
            fma2(acc[3][4], h3, w45.x); fma2(acc[3][5], h3, w45.y);            \
        }                                                                      \
    }

__global__ __launch_bounds__(128, 4) void kA(
    const float* __restrict__ qh, const float* __restrict__ ph, const float* __restrict__ nh,
    const int* __restrict__ qw, const int* __restrict__ pw, const int* __restrict__ nwid,
    const float* __restrict__ projw)
{
    __shared__ __align__(16) u64 sw[192 * WSLOT];   // 39936 bytes
    for (int idx = threadIdx.x; idx < 768 * 6; idx += 128) {
        int d = idx / 6, j = idx % 6;
        sw[(d >> 2) * WSLOT + (d & 3) * 6 + j] =
            pack2(projw[d * 12 + 2 * j], projw[d * 12 + 2 * j + 1]);
    }
    __syncthreads();

    const int lane = threadIdx.x & 31;
    const int sub  = lane & 7;
    const int grp  = lane >> 3;
    const int gw   = (blockIdx.x * blockDim.x + threadIdx.x) >> 5;
    const int nwarps = (KA_BLOCKS * 128) >> 5;
    const u64* swl = sw + sub * WSLOT;

    for (int p = gw; p < NPASS_TOTAL; p += nwarps) {
        const float* hid; const int* wid; int logL, W, wb, lp;
        if (p < 256)      { hid = qh; wid = qw;   logL = 8; W = 200; wb = 0;    lp = p; }
        else if (p < 768) { hid = ph; wid = pw;   logL = 9; W = 400; wb = 3200; lp = p - 256; }
        else              { hid = nh; wid = nwid; logL = 9; W = 400; wb = 9600; lp = p - 768; }

        const int tokBase = lp << 4;                 // 16 tokens
        const int m = tokBase >> logL;
        const float* hbg = hid + (size_t)tokBase * 768 + (size_t)grp * 768 + sub * 4;

        u64 acc[4][6];
        #pragma unroll
        for (int tt = 0; tt < 4; tt++)
            #pragma unroll
            for (int j = 0; j < 6; j++) acc[tt][j] = 0ull;

        float4 A0, A1, A2, A3, B0, B1, B2, B3, C0, C1, C2, C3;
        KA_LD(0, A0, A1, A2, A3);
        KA_LD(1, B0, B1, B2, B3);

        #pragma unroll 1
        for (int i = 0; i < 21; i += 3) {
            KA_LD(i + 2, C0, C1, C2, C3);
            KA_COMPUTE(i, A0, A1, A2, A3);
            KA_LD(i + 3, A0, A1, A2, A3);
            KA_COMPUTE(i + 1, B0, B1, B2, B3);
            KA_LD(i + 4, B0, B1, B2, B3);
            KA_COMPUTE(i + 2, C0, C1, C2, C3);
        }
        KA_LD(23, C0, C1, C2, C3);
        KA_COMPUTE(21, A0, A1, A2, A3);
        KA_COMPUTE(22, B0, B1, B2, B3);
        KA_COMPUTE(23, C0, C1, C2, C3);

        // reduce across the 8 sub-lanes (xor 1,2,4 stay inside the octet)
        #pragma unroll
        for (int tt = 0; tt < 4; tt++)
            #pragma unroll
            for (int j = 0; j < 6; j++) {
                u64 v = acc[tt][j];
                v = add2(v, __shfl_xor_sync(0xffffffffu, v, 1));
                v = add2(v, __shfl_xor_sync(0xffffffffu, v, 2));
                v = add2(v, __shfl_xor_sync(0xffffffffu, v, 4));
                acc[tt][j] = v;
            }

        if (sub == 0) {
            #pragma unroll
            for (int tt = 0; tt < 4; tt++) {
                int tok = tokBase + grp + 4 * tt;
                float* ls = g_acc + (size_t)(wb + m * W + wid[tok]) * 16;
                #pragma unroll
                for (int j = 0; j < 6; j++) {
                    float2 f = unpack2(acc[tt][j]);
                    atomicAdd(ls + 2 * j,     f.x);
                    atomicAdd(ls + 2 * j + 1, f.y);
                }
                atomicAdd(ls + 12, 1.0f);
            }
        }
    }
}

// ---------------------------------------------------------------------------
// Kernel B: per sample — scope softmax -> importance, masked word softmax ->
// per-word coefficient weight/count; writes q/p logits. 144 blocks x 128.
// g_acc pitch-16 layout -> 3 aligned LDG.128 + 1 scalar per word (parallel
// issue, no serial 13-load chain).
// ---------------------------------------------------------------------------
__global__ __launch_bounds__(128) void kB(const float* __restrict__ projb,
                                          const float* __restrict__ simp,
                                          float* __restrict__ out)
{
    const int blk = blockIdx.x;
    int W, wb; float* lout = nullptr;
    if (blk < 16)      { W = 200; wb = blk * 200;                    lout = out + OFF_QLOG + blk * 200 * 12; }
    else if (blk < 32) { int m = blk - 16; W = 400; wb = 3200 + m * 400; lout = out + OFF_PLOG + m * 400 * 12; }
    else               { int m = blk - 32; W = 400; wb = 9600 + m * 400; }

    __shared__ float impbuf[400];
    __shared__ float red[4];
    const int tid = threadIdx.x;

    float b[12], si[12];
    #pragma unroll
    for (int s = 0; s < 12; s++) { b[s] = projb[s]; si[s] = simp[s]; }

    for (int w = tid; w < W; w += 128) {
        const float4* ls4 = (const float4*)(g_acc + (size_t)(wb + w) * 16);
        float4 v0 = ls4[0];
        float4 v1 = ls4[1];
        float4 v2 = ls4[2];
        float  c  = ((const float*)ls4)[12];
        float imp;
        if (c > 0.f) {
            float l[12], mx = -1e30f;
            float invc = 1.f / c;
            l[0] = v0.x * invc + b[0];  l[1] = v0.y * invc + b[1];
            l[2] = v0.z * invc + b[2];  l[3] = v0.w * invc + b[3];
            l[4] = v1.x * invc + b[4];  l[5] = v1.y * invc + b[5];
            l[6] = v1.z * invc + b[6];  l[7] = v1.w * invc + b[7];
            l[8] = v2.x * invc + b[8];  l[9] = v2.y * invc + b[9];
            l[10] = v2.z * invc + b[10]; l[11] = v2.w * invc + b[11];
            #pragma unroll
            for (int s = 0; s < 12; s++) mx = fmaxf(mx, l[s]);
            float se = 0.f, ai = 0.f;
            #pragma unroll
            for (int s = 0; s < 12; s++) {
                float e = __expf(l[s] - mx);
                se += e; ai += e * si[s];
            }
            imp = ai / se;
            if (lout) {
                #pragma unroll
                for (int s = 0; s < 12; s++) lout[w * 12 + s] = l[s];
            }
        } else {
            imp = -1e4f;
            if (lout) {
                #pragma unroll
                for (int s = 0; s < 12; s++) lout[w * 12 + s] = 0.f;
            }
        }
        impbuf[w] = imp;
    }
    __syncthreads();

    float mx = -1e30f;
    for (int w = tid; w < W; w += 128) mx = fmaxf(mx, impbuf[w]);
    #pragma unroll
    for (int o = 16; o; o >>= 1) mx = fmaxf(mx, __shfl_xor_sync(0xffffffffu, mx, o));
    if ((tid & 31) == 0) red[tid >> 5] = mx;
    __syncthreads();
    mx = fmaxf(fmaxf(red[0], red[1]), fmaxf(red[2], red[3]));
    __syncthreads();

    float se = 0.f;
    for (int w = tid; w < W; w += 128) se += __expf(impbuf[w] - mx);
    #pragma unroll
    for (int o = 16; o; o >>= 1) se += __shfl_xor_sync(0xffffffffu, se, o);
    if ((tid & 31) == 0) red[tid >> 5] = se;
    __syncthreads();
    se = red[0] + red[1] + red[2] + red[3];
    const float inv = 1.f / se;

    for (int w = tid; w < W; w += 128) {
        float c = g_acc[(size_t)(wb + w) * 16 + 12];
        g_coef[wb + w] = (c > 0.f) ? (__expf(impbuf[w] - mx) * inv) / c : 0.f;
    }
}

// ---------------------------------------------------------------------------
// Kernel C: pooled[m,:] += sum over 64-token slab coef[m, wid] * h[m,tok,:]
// 1088 blocks x 192 threads, float4/thread, __ldcg (default caching): ~59%
// of reads hit the L2 residue kA just left behind.
// ---------------------------------------------------------------------------
__global__ __launch_bounds__(192) void kC(
    const float* __restrict__ qh, const float* __restrict__ ph, const float* __restrict__ nh,
    const int* __restrict__ qw, const int* __restrict__ pw, const int* __restrict__ nwid,
    float* __restrict__ out)
{
    const int blk = blockIdx.x;
    const float* hid; const int* wid; int L, wb, m, slab; float* po;
    if (blk < 64)       { m = blk >> 2;  slab = blk & 3; hid = qh; wid = qw;   L = 256; wb = m * 200;        po = out + OFF_QPOOL + m * 768; }
    else if (blk < 192) { int b2 = blk - 64;  m = b2 >> 3; slab = b2 & 7; hid = ph; wid = pw;   L = 512; wb = 3200 + m * 400; po = out + OFF_PPOOL + m * 768; }
    else                { int b2 = blk - 192; m = b2 >> 3; slab = b2 & 7; hid = nh; wid = nwid; L = 512; wb = 9600 + m * 400; po = out + OFF_NPOOL + m * 768; }

    __shared__ float cf[64];
    const int tid = threadIdx.x;
    const int t0 = slab * 64;
    if (tid < 64) cf[tid] = g_coef[wb + wid[m * L + t0 + tid]];
    __syncthreads();

    const float* hp = hid + (size_t)(m * L + t0) * 768 + tid * 4;
    float ax = 0.f, ay = 0.f, az = 0.f, aw = 0.f;
    #pragma unroll 8
    for (int t = 0; t < 64; t++) {
        float c = cf[t];
        float4 v = __ldcg((const float4*)(hp + (size_t)t * 768));
        ax += c * v.x; ay += c * v.y; az += c * v.z; aw += c * v.w;
    }
    float* o = po + tid * 4;
    atomicAdd(o + 0, ax);
    atomicAdd(o + 1, ay);
    atomicAdd(o + 2, az);
    atomicAdd(o + 3, aw);
}

// ---------------------------------------------------------------------------
extern "C" void kernel_launch(void* const* d_in, const int* in_sizes, int n_in,
                              void* d_out, int out_size)
{
    const float* qh    = (const float*)d_in[0];
    const float* ph    = (const float*)d_in[1];
    const float* nh    = (const float*)d_in[2];
    const float* projw = (const float*)d_in[3];
    const float* projb = (const float*)d_in[4];
    const float* simp  = (const float*)d_in[5];
    const int*   qw    = (const int*)d_in[6];
    const int*   pw    = (const int*)d_in[7];
    const int*   nwid  = (const int*)d_in[8];
    float* out = (float*)d_out;

    void* pacc = nullptr; cudaGetSymbolAddress(&pacc, g_acc);
    cudaMemsetAsync(pacc, 0, sizeof(float) * TOTAL_WORDS * 16);
    cudaMemsetAsync(out + OFF_QPOOL, 0, sizeof(float) * 24576);   // q_pooled + p_pooled
    cudaMemsetAsync(out + OFF_NPOOL, 0, sizeof(float) * 86016);   // n_pooled

    kA<<<KA_BLOCKS, 128>>>(qh, ph, nh, qw, pw, nwid, projw);
    kB<<<144, 128>>>(projb, simp, out);
    kC<<<1088, 192>>>(qh, ph, nh, qw, pw, nwid, out);
}

// round 12
// speedup vs baseline: 1.6393x; 1.0710x over previous
#include <cuda_runtime.h>

// ---------------------------------------------------------------------------
// B=16, N=7, Lq=256, Lp=512, D=768, S=12, Wq=200, Wp=400
// word slots: q 3200, p 6400, n 44800 -> 54400
// out floats: q_pooled[0,12288) p_pooled[12288,24576)
//             q_logits[24576,62976) p_logits[62976,139776) n_pooled[139776,225792)
// ---------------------------------------------------------------------------
#define TOTAL_WORDS 54400
#define OFF_QPOOL 0
#define OFF_PPOOL 12288
#define OFF_QLOG  24576
#define OFF_PLOG  62976
#define OFF_NPOOL 139776

// g_acc[w*16 + 0..11] = logit sums, [w*16+12] = count (pitch 16 -> kB reads
// 3 aligned LDG.128 + 1 scalar, parallel issue; 13..15 unused)
__device__ float g_acc[TOTAL_WORDS * 16];
__device__ float g_coef[TOTAL_WORDS];

typedef unsigned long long u64;

__device__ __forceinline__ u64 pack2(float x) {
    u64 r; asm("mov.b64 %0, {%1, %1};" : "=l"(r) : "f"(x)); return r;
}
__device__ __forceinline__ u64 pack2(float lo, float hi) {
    u64 r; asm("mov.b64 %0, {%1, %2};" : "=l"(r) : "f"(lo), "f"(hi)); return r;
}
__device__ __forceinline__ void fma2(u64& a, u64 x, u64 y) {
    asm("fma.rn.f32x2 %0, %1, %2, %0;" : "+l"(a) : "l"(x), "l"(y));
}
__device__ __forceinline__ u64 add2(u64 x, u64 y) {
    u64 r; asm("add.rn.f32x2 %0, %1, %2;" : "=l"(r) : "l"(x), "l"(y)); return r;
}
__device__ __forceinline__ float2 unpack2(u64 v) {
    float2 r; asm("mov.b64 {%0, %1}, %2;" : "=f"(r.x), "=f"(r.y) : "l"(v)); return r;
}

// ---------------------------------------------------------------------------
// Kernel A (champion R6 geometry, __ldcs): per-token projection
// h[768]@W[768x12] + segment atomics.
//   sub = lane&7 covers d = sub*4 + 32*i + k (i 0..23, k 0..3)
//   grp = lane>>3, tokens = grp + 4*tt, tt 0..3 -> 16 tokens/pass
// 3 rotating register buffers; loads issued 2-3 compute blocks ahead.
// Weights: smem chunks [c][k*6+j], pitch 26 u64 (39936B); conflict-free
// LDS.128 (sub byte offsets mod 128 = {0,80,32,112,64,16,96,48}).
// Passes: 69632/16 = 4352; grid 544*4 warps = 2176 -> exactly 2 passes/warp.
// ---------------------------------------------------------------------------
#define WSLOT 26
#define NPASS_TOTAL 4352
#define KA_BLOCKS 544

#define KA_LD(I, V0, V1, V2, V3)                                               \
    {                                                                          \
        V0 = __ldcs((const float4*)(hbg +        (I) * 32));                   \
        V1 = __ldcs((const float4*)(hbg + 3072 + (I) * 32));                   \
        V2 = __ldcs((const float4*)(hbg + 6144 + (I) * 32));                   \
        V3 = __ldcs((const float4*)(hbg + 9216 + (I) * 32));                   \
    }

#define KA_COMPUTE(I, A0, A1, A2, A3)                                          \
    {                                                                          \
        const u64* wr = swl + (I) * (8 * WSLOT);                               \
        _Pragma("unroll")                                                      \
        for (int k = 0; k < 4; k++) {                                          \
            u64 h0 = pack2(((const float*)&A0)[k]);                            \
            u64 h1 = pack2(((const float*)&A1)[k]);                            \
            u64 hv2 = pack2(((const float*)&A2)[k]);                           \
            u64 h3 = pack2(((const float*)&A3)[k]);                            \
            ulonglong2 w01 = *(const ulonglong2*)(wr + k * 6);                 \
            ulonglong2 w23 = *(const ulonglong2*)(wr + k * 6 + 2);             \
            ulonglong2 w45 = *(const ulonglong2*)(wr + k * 6 + 4);             \
            fma2(acc[0][0], h0, w01.x); fma2(acc[0][1], h0, w01.y);            \
            fma2(acc[0][2], h0, w23.x); fma2(acc[0][3], h0, w23.y);            \
            fma2(acc[0][4], h0, w45.x); fma2(acc[0][5], h0, w45.y);            \
            fma2(acc[1][0], h1, w01.x); fma2(acc[1][1], h1, w01.y);            \
            fma2(acc[1][2], h1, w23.x); fma2(acc[1][3], h1, w23.y);            \
            fma2(acc[1][4], h1, w45.x); fma2(acc[1][5], h1, w45.y);            \
            fma2(acc[2][0], hv2, w01.x); fma2(acc[2][1], hv2, w01.y);          \
            fma2(acc[2][2], hv2, w23.x); fma2(acc[2][3], hv2, w23.y);          \
            fma2(acc[2][4], hv2, w45.x); fma2(acc[2][5], hv2, w45.y);          \
            fma2(acc[3][0], h3, w01.x); fma2(acc[3][1], h3, w01.y);            \
            fma2(acc[3][2], h3, w23.x); fma2(acc[3][3], h3, w23.y);            \
            fma2(acc[3][4], h3, w45.x); fma2(acc[3][5], h3, w45.y);            \
        }                                                                      \
    }

__global__ __launch_bounds__(128, 4) void kA(
    const float* __restrict__ qh, const float* __restrict__ ph, const float* __restrict__ nh,
    const int* __restrict__ qw, const int* __restrict__ pw, const int* __restrict__ nwid,
    const float* __restrict__ projw)
{
    __shared__ __align__(16) u64 sw[192 * WSLOT];   // 39936 bytes
    for (int idx = threadIdx.x; idx < 768 * 6; idx += 128) {
        int d = idx / 6, j = idx % 6;
        sw[(d >> 2) * WSLOT + (d & 3) * 6 + j] =
            pack2(projw[d * 12 + 2 * j], projw[d * 12 + 2 * j + 1]);
    }
    __syncthreads();

    const int lane = threadIdx.x & 31;
    const int sub  = lane & 7;
    const int grp  = lane >> 3;
    const int gw   = (blockIdx.x * blockDim.x + threadIdx.x) >> 5;
    const int nwarps = (KA_BLOCKS * 128) >> 5;
    const u64* swl = sw + sub * WSLOT;

    for (int p = gw; p < NPASS_TOTAL; p += nwarps) {
        const float* hid; const int* wid; int logL, W, wb, lp;
        if (p < 256)      { hid = qh; wid = qw;   logL = 8; W = 200; wb = 0;    lp = p; }
        else if (p < 768) { hid = ph; wid = pw;   logL = 9; W = 400; wb = 3200; lp = p - 256; }
        else              { hid = nh; wid = nwid; logL = 9; W = 400; wb = 9600; lp = p - 768; }

        const int tokBase = lp << 4;                 // 16 tokens
        const int m = tokBase >> logL;
        const float* hbg = hid + (size_t)tokBase * 768 + (size_t)grp * 768 + sub * 4;

        u64 acc[4][6];
        #pragma unroll
        for (int tt = 0; tt < 4; tt++)
            #pragma unroll
            for (int j = 0; j < 6; j++) acc[tt][j] = 0ull;

        float4 A0, A1, A2, A3, B0, B1, B2, B3, C0, C1, C2, C3;
        KA_LD(0, A0, A1, A2, A3);
        KA_LD(1, B0, B1, B2, B3);

        #pragma unroll 1
        for (int i = 0; i < 21; i += 3) {
            KA_LD(i + 2, C0, C1, C2, C3);
            KA_COMPUTE(i, A0, A1, A2, A3);
            KA_LD(i + 3, A0, A1, A2, A3);
            KA_COMPUTE(i + 1, B0, B1, B2, B3);
            KA_LD(i + 4, B0, B1, B2, B3);
            KA_COMPUTE(i + 2, C0, C1, C2, C3);
        }
        KA_LD(23, C0, C1, C2, C3);
        KA_COMPUTE(21, A0, A1, A2, A3);
        KA_COMPUTE(22, B0, B1, B2, B3);
        KA_COMPUTE(23, C0, C1, C2, C3);

        // reduce across the 8 sub-lanes (xor 1,2,4 stay inside the octet)
        #pragma unroll
        for (int tt = 0; tt < 4; tt++)
            #pragma unroll
            for (int j = 0; j < 6; j++) {
                u64 v = acc[tt][j];
                v = add2(v, __shfl_xor_sync(0xffffffffu, v, 1));
                v = add2(v, __shfl_xor_sync(0xffffffffu, v, 2));
                v = add2(v, __shfl_xor_sync(0xffffffffu, v, 4));
                acc[tt][j] = v;
            }

        if (sub == 0) {
            #pragma unroll
            for (int tt = 0; tt < 4; tt++) {
                int tok = tokBase + grp + 4 * tt;
                float* ls = g_acc + (size_t)(wb + m * W + wid[tok]) * 16;
                #pragma unroll
                for (int j = 0; j < 6; j++) {
                    float2 f = unpack2(acc[tt][j]);
                    atomicAdd(ls + 2 * j,     f.x);
                    atomicAdd(ls + 2 * j + 1, f.y);
                }
                atomicAdd(ls + 12, 1.0f);
            }
        }
    }
}

// ---------------------------------------------------------------------------
// Kernel B: per sample — scope softmax -> importance, masked word softmax ->
// per-word coefficient weight/count; writes q/p logits. 144 blocks x 128.
// pitch-16 g_acc: per-word read = 3x LDG.128 + 1 LDG.32, all parallel.
// ---------------------------------------------------------------------------
__global__ __launch_bounds__(128) void kB(const float* __restrict__ projb,
                                          const float* __restrict__ simp,
                                          float* __restrict__ out)
{
    const int blk = blockIdx.x;
    int W, wb; float* lout = nullptr;
    if (blk < 16)      { W = 200; wb = blk * 200;                    lout = out + OFF_QLOG + blk * 200 * 12; }
    else if (blk < 32) { int m = blk - 16; W = 400; wb = 3200 + m * 400; lout = out + OFF_PLOG + m * 400 * 12; }
    else               { int m = blk - 32; W = 400; wb = 9600 + m * 400; }

    __shared__ float impbuf[400];
    __shared__ float red[4];
    const int tid = threadIdx.x;

    float b[12], si[12];
    #pragma unroll
    for (int s = 0; s < 12; s++) { b[s] = projb[s]; si[s] = simp[s]; }

    for (int w = tid; w < W; w += 128) {
        const float4* ls4 = (const float4*)(g_acc + (size_t)(wb + w) * 16);
        float4 v0 = ls4[0];
        float4 v1 = ls4[1];
        float4 v2 = ls4[2];
        float  c  = ((const float*)ls4)[12];
        float imp;
        if (c > 0.f) {
            float l[12], mx = -1e30f;
            float invc = 1.f / c;
            l[0] = v0.x * invc + b[0];  l[1] = v0.y * invc + b[1];
            l[2] = v0.z * invc + b[2];  l[3] = v0.w * invc + b[3];
            l[4] = v1.x * invc + b[4];  l[5] = v1.y * invc + b[5];
            l[6] = v1.z * invc + b[6];  l[7] = v1.w * invc + b[7];
            l[8] = v2.x * invc + b[8];  l[9] = v2.y * invc + b[9];
            l[10] = v2.z * invc + b[10]; l[11] = v2.w * invc + b[11];
            #pragma unroll
            for (int s = 0; s < 12; s++) mx = fmaxf(mx, l[s]);
            float se = 0.f, ai = 0.f;
            #pragma unroll
            for (int s = 0; s < 12; s++) {
                float e = __expf(l[s] - mx);
                se += e; ai += e * si[s];
            }
            imp = ai / se;
            if (lout) {
                #pragma unroll
                for (int s = 0; s < 12; s++) lout[w * 12 + s] = l[s];
            }
        } else {
            imp = -1e4f;
            if (lout) {
                #pragma unroll
                for (int s = 0; s < 12; s++) lout[w * 12 + s] = 0.f;
            }
        }
        impbuf[w] = imp;
    }
    __syncthreads();

    float mx = -1e30f;
    for (int w = tid; w < W; w += 128) mx = fmaxf(mx, impbuf[w]);
    #pragma unroll
    for (int o = 16; o; o >>= 1) mx = fmaxf(mx, __shfl_xor_sync(0xffffffffu, mx, o));
    if ((tid & 31) == 0) red[tid >> 5] = mx;
    __syncthreads();
    mx = fmaxf(fmaxf(red[0], red[1]), fmaxf(red[2], red[3]));
    __syncthreads();

    float se = 0.f;
    for (int w = tid; w < W; w += 128) se += __expf(impbuf[w] - mx);
    #pragma unroll
    for (int o = 16; o; o >>= 1) se += __shfl_xor_sync(0xffffffffu, se, o);
    if ((tid & 31) == 0) red[tid >> 5] = se;
    __syncthreads();
    se = red[0] + red[1] + red[2] + red[3];
    const float inv = 1.f / se;

    for (int w = tid; w < W; w += 128) {
        float c = g_acc[(size_t)(wb + w) * 16 + 12];
        g_coef[wb + w] = (c > 0.f) ? (__expf(impbuf[w] - mx) * inv) / c : 0.f;
    }
}

// ---------------------------------------------------------------------------
// Kernel C: pooled[m,:] += sum over 64-token slab coef[m, wid] * h[m,tok,:]
// 1088 blocks x 192 threads, float4/thread, __ldcs streaming (champion
// config: evict-first is fastest for this 214MB single-use stream).
// ---------------------------------------------------------------------------
__global__ __launch_bounds__(192) void kC(
    const float* __restrict__ qh, const float* __restrict__ ph, const float* __restrict__ nh,
    const int* __restrict__ qw, const int* __restrict__ pw, const int* __restrict__ nwid,
    float* __restrict__ out)
{
    const int blk = blockIdx.x;
    const float* hid; const int* wid; int L, wb, m, slab; float* po;
    if (blk < 64)       { m = blk >> 2;  slab = blk & 3; hid = qh; wid = qw;   L = 256; wb = m * 200;        po = out + OFF_QPOOL + m * 768; }
    else if (blk < 192) { int b2 = blk - 64;  m = b2 >> 3; slab = b2 & 7; hid = ph; wid = pw;   L = 512; wb = 3200 + m * 400; po = out + OFF_PPOOL + m * 768; }
    else                { int b2 = blk - 192; m = b2 >> 3; slab = b2 & 7; hid = nh; wid = nwid; L = 512; wb = 9600 + m * 400; po = out + OFF_NPOOL + m * 768; }

    __shared__ float cf[64];
    const int tid = threadIdx.x;
    const int t0 = slab * 64;
    if (tid < 64) cf[tid] = g_coef[wb + wid[m * L + t0 + tid]];
    __syncthreads();

    const float* hp = hid + (size_t)(m * L + t0) * 768 + tid * 4;
    float ax = 0.f, ay = 0.f, az = 0.f, aw = 0.f;
    #pragma unroll 8
    for (int t = 0; t < 64; t++) {
        float c = cf[t];
        float4 v = __ldcs((const float4*)(hp + (size_t)t * 768));
        ax += c * v.x; ay += c * v.y; az += c * v.z; aw += c * v.w;
    }
    float* o = po + tid * 4;
    atomicAdd(o + 0, ax);
    atomicAdd(o + 1, ay);
    atomicAdd(o + 2, az);
    atomicAdd(o + 3, aw);
}

// ---------------------------------------------------------------------------
extern "C" void kernel_launch(void* const* d_in, const int* in_sizes, int n_in,
                              void* d_out, int out_size)
{
    const float* qh    = (const float*)d_in[0];
    const float* ph    = (const float*)d_in[1];
    const float* nh    = (const float*)d_in[2];
    const float* projw = (const float*)d_in[3];
    const float* projb = (const float*)d_in[4];
    const float* simp  = (const float*)d_in[5];
    const int*   qw    = (const int*)d_in[6];
    const int*   pw    = (const int*)d_in[7];
    const int*   nwid  = (const int*)d_in[8];
    float* out = (float*)d_out;

    void* pacc = nullptr; cudaGetSymbolAddress(&pacc, g_acc);
    cudaMemsetAsync(pacc, 0, sizeof(float) * TOTAL_WORDS * 16);
    cudaMemsetAsync(out + OFF_QPOOL, 0, sizeof(float) * 24576);   // q_pooled + p_pooled
    cudaMemsetAsync(out + OFF_NPOOL, 0, sizeof(float) * 86016);   // n_pooled

    kA<<<KA_BLOCKS, 128>>>(qh, ph, nh, qw, pw, nwid, projw);
    kB<<<144, 128>>>(projb, simp, out);
    kC<<<1088, 192>>>(qh, ph, nh, qw, pw, nwid, out);
}